// round 12
// baseline (speedup 1.0000x reference)
#include <cuda_runtime.h>
#include <math.h>
#include <float.h>
#include <stdint.h>

#define N_SEQ 1024
#define DIM   1024
#define HEADS 16
#define KV_HEADS 4
#define DH    64
#define BS    32
#define NUM_SEL 8
#define W_BLK 32
#define GQ    4
#define CDIM  2048
#define HID   2048
#define QKV_COLS 1536
#define SCALE 0.125f
#define NSEL1 9
#define JTOT  288
#define CW    33

// ---------------- scratch ----------------
__device__ float g_x[N_SEQ*DIM];
__device__ float g_qkv[N_SEQ*QKV_COLS];
__device__ float g_kpe[KV_HEADS*W_BLK*CDIM];
__device__ float g_vpe[KV_HEADS*W_BLK*CDIM];
__device__ float g_hk[KV_HEADS*W_BLK*HID];
__device__ float g_hv[KV_HEADS*W_BLK*HID];
__device__ float g_ckm[KV_HEADS*W_BLK*DH];
__device__ float g_cvm[KV_HEADS*W_BLK*DH];
__device__ float g_csim[HEADS*N_SEQ*CW];
__device__ float g_cout[N_SEQ*HEADS*DH];
__device__ float g_fout[N_SEQ*HEADS*DH];
__device__ int   g_selidx[KV_HEADS*N_SEQ*NSEL1];
__device__ int   g_selmask[KV_HEADS*N_SEQ*NSEL1];
__device__ float g_gates[N_SEQ*2*HEADS];
__device__ float g_comb[N_SEQ*HEADS*DH];

// ---------------- helpers ----------------
__device__ __forceinline__ float warpMax(float v) {
    #pragma unroll
    for (int o = 16; o; o >>= 1) v = fmaxf(v, __shfl_xor_sync(0xffffffffu, v, o));
    return v;
}
__device__ __forceinline__ float warpSum(float v) {
    #pragma unroll
    for (int o = 16; o; o >>= 1) v += __shfl_xor_sync(0xffffffffu, v, o);
    return v;
}
__device__ __forceinline__ uint32_t f2tf32(float f) {
    uint32_t u;
    asm("cvt.rna.tf32.f32 %0, %1;" : "=r"(u) : "f"(f));
    return u;
}
__device__ __forceinline__ float2 split2_tf32(float v) {
    uint32_t hi = f2tf32(v);
    uint32_t lo = f2tf32(v - __uint_as_float(hi));
    return make_float2(__uint_as_float(hi), __uint_as_float(lo));
}
__device__ __forceinline__ void mma_tf32(float* c, const uint32_t* a, const uint32_t* b) {
    asm volatile(
        "mma.sync.aligned.m16n8k8.row.col.f32.tf32.tf32.f32 "
        "{%0,%1,%2,%3},{%4,%5,%6,%7},{%8,%9},{%0,%1,%2,%3};"
        : "+f"(c[0]), "+f"(c[1]), "+f"(c[2]), "+f"(c[3])
        : "r"(a[0]), "r"(a[1]), "r"(a[2]), "r"(a[3]), "r"(b[0]), "r"(b[1]));
}
__device__ __forceinline__ void cp16(void* smem_dst, const void* gsrc, int src_size) {
    uint32_t d = (uint32_t)__cvta_generic_to_shared(smem_dst);
    asm volatile("cp.async.ca.shared.global [%0], [%1], 16, %2;"
                 :: "r"(d), "l"(gsrc), "r"(src_size));
}

// ---------------- RMSNorm ----------------
__global__ void rmsnorm_kernel(const float* __restrict__ inp,
                               const float* __restrict__ gw) {
    int n = blockIdx.x;
    int t = threadIdx.x;
    const float* row = inp + n * DIM;
    float s = 0.f;
    for (int c = t; c < DIM; c += 256) { float v = row[c]; s += v * v; }
    s = warpSum(s);
    __shared__ float wbuf[8];
    int lane = t & 31, wid = t >> 5;
    if (lane == 0) wbuf[wid] = s;
    __syncthreads();
    if (t == 0) {
        float tot = 0.f;
        #pragma unroll
        for (int i = 0; i < 8; i++) tot += wbuf[i];
        wbuf[0] = rsqrtf(tot / (float)DIM + 1e-6f);
    }
    __syncthreads();
    float r = wbuf[0];
    float* xr = g_x + n * DIM;
    for (int c = t; c < DIM; c += 256) xr[c] = row[c] * r * gw[c];
}

// ---------------- tf32x3 GEMM: cp.async pipeline + shared pre-split ---------
// C = A@B (+bias), A: MxK row-major (M%128==0, K%16==0), B: KxN row-major.
// BM=128, BN=64, BK=16, 256 threads (8 warps, 4Mx2N).
// Per tile: cooperative split of A/B into (hi,lo) float2 smem once; mainloop
// is pure LDS.64 + HMMA (no cvt). blockIdx.z = sel*S + split (dual-operand +
// split-K). ATOMIC: atomicAdd into bias-pre-init C. RELUA: relu before split.
// Dynamic smem layout (floats):
//   rawA [2][128][20]  @ 0      (5120)
//   rawB [2][16][72]   @ 5120   (2304)
//   spA  [128][20] f2  @ 7424   (5120)
//   spB  [16][68]  f2  @ 12544  (2176)
#define GEMM_SMEM_FLOATS 14720
#define GEMM_SMEM_BYTES  (GEMM_SMEM_FLOATS * 4)

template <int ATOMIC, int RELUA>
__global__ void __launch_bounds__(256)
mma_gemm(const float* __restrict__ A0, const float* __restrict__ A1,
         const float* __restrict__ B0, const float* __restrict__ B1,
         const float* __restrict__ bias0, const float* __restrict__ bias1,
         float* __restrict__ C0, float* __restrict__ C1,
         int M, int N, int K, int S) {
    extern __shared__ float smem[];
    float (*rawA)[128][20] = reinterpret_cast<float(*)[128][20]>(smem);
    float (*rawB)[16][72]  = reinterpret_cast<float(*)[16][72]>(smem + 5120);
    float2 (*spA)[20]      = reinterpret_cast<float2(*)[20]>(smem + 7424);
    float2 (*spB)[68]      = reinterpret_cast<float2(*)[68]>(smem + 12544);

    int z = blockIdx.z;
    int sel = z / S, sp = z - sel * S;
    const float* A = sel ? A1 : A0;
    const float* B = sel ? B1 : B0;
    const float* bias = sel ? bias1 : bias0;
    float* C = sel ? C1 : C0;
    int Kc = K / S;
    int kb = sp * Kc;

    int tid = threadIdx.x;
    int lane = tid & 31, warp = tid >> 5;
    int wm = warp & 3, wn = warp >> 2;
    int m0 = blockIdx.y * 128, n0 = blockIdx.x * 64;

    int ar0 = tid >> 2,          ac0 = (tid & 3) * 4;
    int ar1 = (tid + 256) >> 2,  ac1 = ac0;
    int bkr = tid >> 4,          bnc = (tid & 15) * 4;
    int bgn = n0 + bnc;
    int bsz = (bgn < N) ? 16 : 0;   // src_size 0 => zero-fill smem

    float acc[2][4][4];
    #pragma unroll
    for (int i = 0; i < 2; i++)
        #pragma unroll
        for (int j = 0; j < 4; j++)
            #pragma unroll
            for (int l = 0; l < 4; l++) acc[i][j][l] = 0.f;

    int ntiles = Kc / 16;

    // prologue: issue tile 0
    {
        int k0 = kb;
        cp16(&rawA[0][ar0][ac0], A + (m0 + ar0) * K + k0 + ac0, 16);
        cp16(&rawA[0][ar1][ac1], A + (m0 + ar1) * K + k0 + ac1, 16);
        cp16(&rawB[0][bkr][bnc], B + (k0 + bkr) * N + (bsz ? bgn : 0), bsz);
        asm volatile("cp.async.commit_group;");
    }

    for (int it = 0; it < ntiles; it++) {
        int buf = it & 1;
        if (it + 1 < ntiles) {
            int k0 = kb + (it + 1) * 16;
            int nb = buf ^ 1;
            cp16(&rawA[nb][ar0][ac0], A + (m0 + ar0) * K + k0 + ac0, 16);
            cp16(&rawA[nb][ar1][ac1], A + (m0 + ar1) * K + k0 + ac1, 16);
            cp16(&rawB[nb][bkr][bnc], B + (k0 + bkr) * N + (bsz ? bgn : 0), bsz);
            asm volatile("cp.async.commit_group;");
            asm volatile("cp.async.wait_group 1;");
        } else {
            asm volatile("cp.async.wait_group 0;");
        }
        __syncthreads();

        // cooperative split: A 2048 values, B 1024 values
        #pragma unroll
        for (int i = 0; i < 8; i++) {
            int q = tid + i * 256;
            int r = q >> 4, c = q & 15;
            float v = rawA[buf][r][c];
            if (RELUA) v = fmaxf(v, 0.f);
            spA[r][c] = split2_tf32(v);
        }
        #pragma unroll
        for (int i = 0; i < 4; i++) {
            int q = tid + i * 256;
            int r = q >> 6, c = q & 63;
            spB[r][c] = split2_tf32(rawB[buf][r][c]);
        }
        __syncthreads();

        #pragma unroll
        for (int ks = 0; ks < 2; ks++) {
            int kbase = ks * 8;
            uint32_t ahi[2][4], alo[2][4], bhi[4][2], blo[4][2];
            #pragma unroll
            for (int mt = 0; mt < 2; mt++) {
                int am = wm * 32 + mt * 16 + (lane >> 2);
                int c = kbase + (lane & 3);
                float2 v0 = spA[am][c];
                float2 v1 = spA[am + 8][c];
                float2 v2 = spA[am][c + 4];
                float2 v3 = spA[am + 8][c + 4];
                ahi[mt][0] = __float_as_uint(v0.x); alo[mt][0] = __float_as_uint(v0.y);
                ahi[mt][1] = __float_as_uint(v1.x); alo[mt][1] = __float_as_uint(v1.y);
                ahi[mt][2] = __float_as_uint(v2.x); alo[mt][2] = __float_as_uint(v2.y);
                ahi[mt][3] = __float_as_uint(v3.x); alo[mt][3] = __float_as_uint(v3.y);
            }
            #pragma unroll
            for (int nt = 0; nt < 4; nt++) {
                int bn = wn * 32 + nt * 8 + (lane >> 2);
                int r = kbase + (lane & 3);
                float2 w0 = spB[r][bn];
                float2 w1 = spB[r + 4][bn];
                bhi[nt][0] = __float_as_uint(w0.x); blo[nt][0] = __float_as_uint(w0.y);
                bhi[nt][1] = __float_as_uint(w1.x); blo[nt][1] = __float_as_uint(w1.y);
            }
            #pragma unroll
            for (int mt = 0; mt < 2; mt++)
                #pragma unroll
                for (int nt = 0; nt < 4; nt++) {
                    mma_tf32(acc[mt][nt], alo[mt], bhi[nt]);
                    mma_tf32(acc[mt][nt], ahi[mt], blo[nt]);
                    mma_tf32(acc[mt][nt], ahi[mt], bhi[nt]);
                }
        }
        __syncthreads();
    }

    #pragma unroll
    for (int mt = 0; mt < 2; mt++) {
        int row = m0 + wm * 32 + mt * 16 + (lane >> 2);
        #pragma unroll
        for (int nt = 0; nt < 4; nt++) {
            int col = n0 + wn * 32 + nt * 8 + (lane & 3) * 2;
            if (col >= N) continue;
            float* a4 = acc[mt][nt];
            if (ATOMIC) {
                atomicAdd(&C[row * N + col],           a4[0]);
                atomicAdd(&C[row * N + col + 1],       a4[1]);
                atomicAdd(&C[(row + 8) * N + col],     a4[2]);
                atomicAdd(&C[(row + 8) * N + col + 1], a4[3]);
            } else {
                float b0 = bias ? bias[col] : 0.f;
                float b1 = bias ? bias[col + 1] : 0.f;
                C[row * N + col]           = a4[0] + b0;
                C[row * N + col + 1]       = a4[1] + b1;
                C[(row + 8) * N + col]     = a4[2] + b0;
                C[(row + 8) * N + col + 1] = a4[3] + b1;
            }
        }
    }
}

// ---------------- bias pre-init for split-K atomic targets ------------------
#define SEG1 (128*HID)
#define SEG2 (2*128*HID)
#define SEG3 (SEG2 + 128*DH)
#define SEG4 (SEG2 + 2*128*DH)
#define SEGT (SEG4 + N_SEQ*32)
__global__ void init_bias_kernel(const float* __restrict__ kb1, const float* __restrict__ vb1,
                                 const float* __restrict__ kb2, const float* __restrict__ vb2,
                                 const float* __restrict__ gb) {
    int idx = blockIdx.x * 256 + threadIdx.x;
    if (idx >= SEGT) return;
    if (idx < SEG1)      g_hk[idx] = kb1[idx & (HID - 1)];
    else if (idx < SEG2) g_hv[idx - SEG1] = vb1[idx & (HID - 1)];
    else if (idx < SEG3) g_ckm[idx - SEG2] = kb2[idx & (DH - 1)];
    else if (idx < SEG4) g_cvm[idx - SEG3] = vb2[idx & (DH - 1)];
    else                 g_gates[idx - SEG4] = gb[idx & 31];
}

// ---------------- compressed attention: block per (n, kv), 4 heads ----------
__global__ void cattn_kernel(const float* __restrict__ mem_kv) {
    int n = blockIdx.x, kv = blockIdx.y;
    int t = threadIdx.x;
    int lane = t & 31, w = t >> 5;
    __shared__ float qs[GQ][64];
    __shared__ float ks[CW][65];
    __shared__ float vs[CW][65];
    __shared__ float ps[GQ][CW];

    qs[w][lane]      = g_qkv[n * QKV_COLS + (kv * GQ + w) * 64 + lane];
    qs[w][lane + 32] = g_qkv[n * QKV_COLS + (kv * GQ + w) * 64 + lane + 32];
    for (int i = t; i < CW * 16; i += 128) {
        int j = i >> 4, c4 = (i & 15) * 4;
        const float* ksrc = (j == 0) ? (mem_kv + kv * DH)
                                     : (g_ckm + (kv * W_BLK + j - 1) * DH);
        const float* vsrc = (j == 0) ? (mem_kv + KV_HEADS * DH + kv * DH)
                                     : (g_cvm + (kv * W_BLK + j - 1) * DH);
        float4 fk = *reinterpret_cast<const float4*>(ksrc + c4);
        float4 fv = *reinterpret_cast<const float4*>(vsrc + c4);
        ks[j][c4] = fk.x; ks[j][c4+1] = fk.y; ks[j][c4+2] = fk.z; ks[j][c4+3] = fk.w;
        vs[j][c4] = fv.x; vs[j][c4+1] = fv.y; vs[j][c4+2] = fv.z; vs[j][c4+3] = fv.w;
    }
    __syncthreads();

    for (int j = lane; j < CW; j += 32) {
        float acc = 0.f;
        #pragma unroll
        for (int d = 0; d < 64; d++) acc += ks[j][d] * qs[w][d];
        acc *= SCALE;
        ps[w][j] = acc;
        g_csim[((kv * GQ + w) * N_SEQ + n) * CW + j] = acc;
    }
    __syncwarp();
    float m = -FLT_MAX;
    for (int j = lane; j < CW; j += 32) m = fmaxf(m, ps[w][j]);
    m = warpMax(m);
    float z = 0.f;
    for (int j = lane; j < CW; j += 32) {
        float e = expf(ps[w][j] - m);
        ps[w][j] = e;
        z += e;
    }
    z = warpSum(z);
    float inv = 1.f / z;
    __syncwarp();
    float acc0 = 0.f, acc1 = 0.f;
    for (int j = 0; j < CW; j++) {
        float p = ps[w][j];
        acc0 += p * vs[j][lane];
        acc1 += p * vs[j][lane + 32];
    }
    int hg = kv * GQ + w;
    g_cout[n * (HEADS * DH) + hg * 64 + lane]      = acc0 * inv;
    g_cout[n * (HEADS * DH) + hg * 64 + lane + 32] = acc1 * inv;
}

// ---------------- rotary in-place on q/k ------------------------------------
__global__ void rotary_kernel() {
    int idx = blockIdx.x * 256 + threadIdx.x;
    int n = idx / 640;
    int p = idx - n * 640;
    int col = p * 2;
    int i = (col & 63) >> 1;
    float inv = exp2f(-13.287712379549449f * (float)i / 32.f);
    float ang = (float)n * inv;
    float cs = cosf(ang), sn = sinf(ang);
    float* ptr = g_qkv + n * QKV_COLS + col;
    float x0 = ptr[0], x1 = ptr[1];
    ptr[0] = x0 * cs - x1 * sn;
    ptr[1] = x1 * cs + x0 * sn;
}

// ---------------- top-k block selection -------------------------------------
__global__ void select_kernel() {
    int id = blockIdx.x * 256 + threadIdx.x;
    if (id >= KV_HEADS * N_SEQ) return;
    int kv = id >> 10, n = id & 1023;
    float imp[W_BLK];
    #pragma unroll
    for (int w = 0; w < W_BLK; w++) {
        float s = 0.f;
        #pragma unroll
        for (int g = 0; g < GQ; g++)
            s += g_csim[((kv * GQ + g) * N_SEQ + n) * CW + 1 + w];
        imp[w] = s * 0.25f;
    }
    float m = -1000.f;
    #pragma unroll
    for (int w = 0; w < W_BLK; w++) m = fmaxf(m, imp[w]);
    float Z = expf(-1000.f - m);
    #pragma unroll
    for (int w = 0; w < W_BLK; w++) Z += expf(imp[w] - m);
    int* si = g_selidx + id * NSEL1;
    int* sm = g_selmask + id * NSEL1;
    bool used[W_BLK];
    #pragma unroll
    for (int w = 0; w < W_BLK; w++) used[w] = false;
    for (int s = 0; s < NUM_SEL; s++) {
        int best = -1; float bv = -FLT_MAX;
        for (int w = 0; w < W_BLK; w++)
            if (!used[w] && imp[w] > bv) { bv = imp[w]; best = w; }
        used[best] = true;
        si[s] = best;
        sm[s] = (expf(bv - m) / Z > 1e-10f) ? 1 : 0;
    }
    si[NUM_SEL] = n >> 5;
    sm[NUM_SEL] = 1;
}

// ---------------- fine attention: block per (n, kv), 4 heads, staged --------
__global__ void fattn_kernel() {
    int n = blockIdx.x, kv = blockIdx.y;
    int t = threadIdx.x;
    int lane = t & 31, w = t >> 5;
    __shared__ float qs[GQ][64];
    __shared__ float stage[BS][65];
    __shared__ float ps[GQ][JTOT];
    __shared__ float pinv[GQ];
    __shared__ int sblk[NSEL1], smk[NSEL1];
    __shared__ float partial[256];

    if (t < 128) {
        int h = t >> 5, l = t & 31;
        qs[h][l]      = g_qkv[n * QKV_COLS + (kv * GQ + h) * 64 + l];
        qs[h][l + 32] = g_qkv[n * QKV_COLS + (kv * GQ + h) * 64 + l + 32];
    }
    if (t < NSEL1) {
        sblk[t] = g_selidx[(kv * N_SEQ + n) * NSEL1 + t];
        smk[t]  = g_selmask[(kv * N_SEQ + n) * NSEL1 + t];
    }
    __syncthreads();

    for (int s = 0; s < NSEL1; s++) {
        int msk = smk[s];
        if (msk) {
            const float* base = g_qkv + (sblk[s] * BS) * QKV_COLS + 1024 + kv * 64;
            for (int i = t; i < 512; i += 256) {
                int r = i >> 4, c4 = (i & 15) * 4;
                float4 f = *reinterpret_cast<const float4*>(base + r * QKV_COLS + c4);
                stage[r][c4] = f.x; stage[r][c4+1] = f.y;
                stage[r][c4+2] = f.z; stage[r][c4+3] = f.w;
            }
        }
        __syncthreads();
        {
            int j = t & 31, h = (t >> 5) & 3, half = t >> 7;
            float acc = 0.f;
            if (msk) {
                int d0 = half * 32;
                #pragma unroll
                for (int d = 0; d < 32; d++) acc += stage[j][d0 + d] * qs[h][d0 + d];
            }
            partial[t] = acc;
        }
        __syncthreads();
        if (t < 128) {
            int j = t & 31, h = t >> 5;
            ps[h][s * BS + j] = msk ? (partial[t] + partial[t + 128]) * SCALE
                                    : -FLT_MAX;
        }
        __syncthreads();
    }

    if (w < GQ) {
        float m = -FLT_MAX;
        for (int j = lane; j < JTOT; j += 32) m = fmaxf(m, ps[w][j]);
        m = warpMax(m);
        float z = 0.f;
        for (int j = lane; j < JTOT; j += 32) {
            float e = expf(ps[w][j] - m);
            ps[w][j] = e;
            z += e;
        }
        z = warpSum(z);
        if (lane == 0) pinv[w] = 1.f / z;
    }
    __syncthreads();

    int h = t >> 6, d = t & 63;
    float acc = 0.f;
    for (int s = 0; s < NSEL1; s++) {
        const float* base = g_qkv + (sblk[s] * BS) * QKV_COLS + 1280 + kv * 64;
        for (int i = t; i < 512; i += 256) {
            int r = i >> 4, c4 = (i & 15) * 4;
            float4 f = *reinterpret_cast<const float4*>(base + r * QKV_COLS + c4);
            stage[r][c4] = f.x; stage[r][c4+1] = f.y;
            stage[r][c4+2] = f.z; stage[r][c4+3] = f.w;
        }
        __syncthreads();
        #pragma unroll
        for (int j = 0; j < BS; j++) acc += ps[h][s * BS + j] * stage[j][d];
        __syncthreads();
    }
    g_fout[n * (HEADS * DH) + (kv * GQ + h) * 64 + d] = acc * pinv[h];
}

// ---------------- build kpe / vpe -------------------------------------------
__global__ void build_pe_kernel(const float* __restrict__ k_pos,
                                const float* __restrict__ v_pos) {
    int idx = blockIdx.x * 256 + threadIdx.x;
    int row = idx >> 11;
    int c = idx & 2047;
    int h = row >> 5, w = row & 31;
    int pos = c >> 6, d = c & 63;
    int n = w * BS + pos;
    const float* base = g_qkv + n * QKV_COLS + h * 64 + d;
    g_kpe[idx] = base[1024] + k_pos[(h * BS + pos) * DH + d];
    g_vpe[idx] = base[1280] + v_pos[(h * BS + pos) * DH + d];
}

// ---------------- gated combine ----------------------------------------------
__global__ void combine_kernel() {
    int idx = blockIdx.x * 256 + threadIdx.x;
    int n = idx >> 10;
    int c = idx & 1023;
    int h = c >> 6;
    float r0 = g_gates[n * (2 * HEADS) + 2 * h];
    float r1 = g_gates[n * (2 * HEADS) + 2 * h + 1];
    float g0 = 1.f / (1.f + expf(-r0));
    float g1 = 1.f / (1.f + expf(-r1));
    g_comb[idx] = g0 * g_cout[idx] + g1 * g_fout[idx];
}

// ---------------- launch ------------------------------------------------------
extern "C" void kernel_launch(void* const* d_in, const int* in_sizes, int n_in,
                              void* d_out, int out_size) {
    const float* inp    = (const float*)d_in[0];
    const float* g_norm = (const float*)d_in[1];
    const float* w_qkv  = (const float*)d_in[2];
    const float* mem_kv = (const float*)d_in[3];
    const float* k_pos  = (const float*)d_in[4];
    const float* v_pos  = (const float*)d_in[5];
    const float* k_w1   = (const float*)d_in[6];
    const float* k_b1   = (const float*)d_in[7];
    const float* k_w2   = (const float*)d_in[8];
    const float* k_b2   = (const float*)d_in[9];
    const float* v_w1   = (const float*)d_in[10];
    const float* v_b1   = (const float*)d_in[11];
    const float* v_w2   = (const float*)d_in[12];
    const float* v_b2   = (const float*)d_in[13];
    const float* gate_w = (const float*)d_in[14];
    const float* gate_b = (const float*)d_in[15];
    const float* w_out  = (const float*)d_in[16];
    float* out = (float*)d_out;

    float *px, *pqkv, *pkpe, *pvpe, *phk, *phv, *pckm, *pcvm, *pgates, *pcomb;
    cudaGetSymbolAddress((void**)&px,     g_x);
    cudaGetSymbolAddress((void**)&pqkv,   g_qkv);
    cudaGetSymbolAddress((void**)&pkpe,   g_kpe);
    cudaGetSymbolAddress((void**)&pvpe,   g_vpe);
    cudaGetSymbolAddress((void**)&phk,    g_hk);
    cudaGetSymbolAddress((void**)&phv,    g_hv);
    cudaGetSymbolAddress((void**)&pckm,   g_ckm);
    cudaGetSymbolAddress((void**)&pcvm,   g_cvm);
    cudaGetSymbolAddress((void**)&pgates, g_gates);
    cudaGetSymbolAddress((void**)&pcomb,  g_comb);

    cudaFuncSetAttribute(mma_gemm<0, 0>, cudaFuncAttributeMaxDynamicSharedMemorySize, GEMM_SMEM_BYTES);
    cudaFuncSetAttribute(mma_gemm<1, 0>, cudaFuncAttributeMaxDynamicSharedMemorySize, GEMM_SMEM_BYTES);
    cudaFuncSetAttribute(mma_gemm<1, 1>, cudaFuncAttributeMaxDynamicSharedMemorySize, GEMM_SMEM_BYTES);

    rmsnorm_kernel<<<N_SEQ, 256>>>(inp, g_norm);
    init_bias_kernel<<<(SEGT + 255) / 256, 256>>>(k_b1, v_b1, k_b2, v_b2, gate_b);
    mma_gemm<0, 0><<<dim3(QKV_COLS / 64, N_SEQ / 128, 1), 256, GEMM_SMEM_BYTES>>>(
        px, px, w_qkv, w_qkv, nullptr, nullptr, pqkv, pqkv, N_SEQ, QKV_COLS, DIM, 1);
    build_pe_kernel<<<(KV_HEADS * W_BLK * CDIM) / 256, 256>>>(k_pos, v_pos);
    mma_gemm<1, 0><<<dim3(HID / 64, 1, 2 * 4), 256, GEMM_SMEM_BYTES>>>(
        pkpe, pvpe, k_w1, v_w1, nullptr, nullptr, phk, phv, 128, HID, CDIM, 4);
    mma_gemm<1, 1><<<dim3(1, 1, 2 * 8), 256, GEMM_SMEM_BYTES>>>(
        phk, phv, k_w2, v_w2, nullptr, nullptr, pckm, pcvm, 128, DH, HID, 8);
    cattn_kernel<<<dim3(N_SEQ, KV_HEADS), 128>>>(mem_kv);
    rotary_kernel<<<(N_SEQ * 640) / 256, 256>>>();
    select_kernel<<<(KV_HEADS * N_SEQ) / 256, 256>>>();
    fattn_kernel<<<dim3(N_SEQ, KV_HEADS), 256>>>();
    mma_gemm<1, 0><<<dim3(1, N_SEQ / 128, 4), 256, GEMM_SMEM_BYTES>>>(
        px, px, gate_w, gate_w, nullptr, nullptr, pgates, pgates, N_SEQ, 32, DIM, 4);
    combine_kernel<<<(N_SEQ * HEADS * DH) / 256, 256>>>();
    mma_gemm<0, 0><<<dim3(DIM / 64, N_SEQ / 128, 1), 256, GEMM_SMEM_BYTES>>>(
        pcomb, pcomb, w_out, w_out, nullptr, nullptr, out, out, N_SEQ, DIM, DIM, 1);
}